// round 2
// baseline (speedup 1.0000x reference)
#include <cuda_runtime.h>
#include <math.h>

constexpr int NB  = 256;    // batch
constexpr int NT  = 800;    // time steps
constexpr int NH  = 512;    // hidden
constexpr int ND  = 128;    // input dim (= vocab)
constexpr int G4  = 4 * NH; // 2048 gate rows
constexpr int NBLK = 136;   // 128 GEMM blocks + 8 logits blocks (all co-resident)

typedef unsigned long long ull;

// ---- persistent device scratch ----
__device__ float g_h0[2][NB * NH];
__device__ float g_h1[2][NB * NH];
__device__ float g_c0[NB * NH];
__device__ float g_c1[NB * NH];
__device__ float g_wih0t[ND * G4];          // W_ih0 transposed: [din][4H]
__device__ volatile unsigned g_bar_count;   // monotone grid barrier counter

__device__ __forceinline__ float sigf(float x) {
    return 1.0f / (1.0f + __expf(-x));
}
__device__ __forceinline__ float tanhf_fast(float x) {
    x = fminf(fmaxf(x, -15.0f), 15.0f);
    float e = __expf(2.0f * x);
    return (e - 1.0f) / (e + 1.0f);
}
__device__ __forceinline__ float warp_max(float v) {
    #pragma unroll
    for (int o = 16; o; o >>= 1) v = fmaxf(v, __shfl_xor_sync(0xffffffffu, v, o));
    return v;
}
__device__ __forceinline__ float warp_sum(float v) {
    #pragma unroll
    for (int o = 16; o; o >>= 1) v += __shfl_xor_sync(0xffffffffu, v, o);
    return v;
}

// ---- init: zero state, transpose W_ih0, reset barrier ----
__global__ void kinit(const float* __restrict__ Wih0) {
    int i = blockIdx.x * blockDim.x + threadIdx.x;
    int stride = gridDim.x * blockDim.x;
    if (i == 0) g_bar_count = 0;
    for (int idx = i; idx < NB * NH; idx += stride) {
        g_h0[0][idx] = 0.f; g_h1[0][idx] = 0.f;
        g_c0[idx] = 0.f;    g_c1[idx] = 0.f;
    }
    for (int idx = i; idx < ND * G4; idx += stride) {
        int k = idx / G4;       // input-dim index
        int j = idx - k * G4;   // gate row
        g_wih0t[idx] = Wih0[j * ND + k];
    }
}

// ---- grid-wide barrier (monotone counter, all NBLK blocks resident) ----
__device__ __forceinline__ void grid_barrier(unsigned target) {
    __threadfence();
    __syncthreads();
    if (threadIdx.x == 0) {
        atomicAdd((unsigned*)&g_bar_count, 1u);
        while (g_bar_count < target) { __nanosleep(64); }
    }
    __syncthreads();
    __threadfence();
}

// ---- 32x(4x32) x K tile GEMM with packed f32x2 FMAs ----
// Output rows of W: g*rowstep + u0 + u   (u in [0,32))
// acc[g][0] packs batch (ty*4+0, ty*4+1), acc[g][1] packs (ty*4+2, ty*4+3),
// column = u0 + lane.
__device__ __forceinline__ void gemm_acc(
    ull acc[4][2],
    const float* __restrict__ act,   // rows b0..b0+31, leading dim NH (read via cg)
    const float* __restrict__ W,     // leading dim NH
    int b0, int u0, int rowstep,
    float (*hs)[34], ull (*ws2)[32][33],
    int lane, int ty)
{
    for (int kk = 0; kk < NH; kk += 32) {
        __syncthreads();
        #pragma unroll
        for (int r = 0; r < 4; r++) {
            int b = ty + r * 8;
            hs[lane][b] = __ldcg(&act[(b0 + b) * NH + kk + lane]);
        }
        #pragma unroll
        for (int g = 0; g < 4; g++) {
            #pragma unroll
            for (int r = 0; r < 4; r++) {
                int u = ty + r * 8;
                float w = W[(g * rowstep + u0 + u) * NH + kk + lane];
                ull p;
                asm("mov.b64 %0, {%1, %1};" : "=l"(p) : "f"(w));
                ws2[g][lane][u] = p;
            }
        }
        __syncthreads();
        #pragma unroll
        for (int k = 0; k < 32; k++) {
            const ull* hk = (const ull*)&hs[k][0];
            ull h01 = hk[ty * 2];
            ull h23 = hk[ty * 2 + 1];
            #pragma unroll
            for (int g = 0; g < 4; g++) {
                ull w = ws2[g][k][lane];
                asm("fma.rn.f32x2 %0, %1, %2, %0;" : "+l"(acc[g][0]) : "l"(w), "l"(h01));
                asm("fma.rn.f32x2 %0, %1, %2, %0;" : "+l"(acc[g][1]) : "l"(w), "l"(h23));
            }
        }
    }
}

union F2U { ull u; float2 f; };

// ---- the persistent kernel: whole 800-step sequence in one launch ----
__global__ __launch_bounds__(256) void lstm_persistent(
    const float* __restrict__ Whh0,
    const float* __restrict__ bih0, const float* __restrict__ bhh0,
    const float* __restrict__ Wih1, const float* __restrict__ Whh1,
    const float* __restrict__ bih1, const float* __restrict__ bhh1,
    const float* __restrict__ Wlin, const float* __restrict__ blin,
    const int* __restrict__ z, const int* __restrict__ nframes,
    float* __restrict__ out)
{
    __shared__ float hs[32][34];
    __shared__ ull ws2[4][32][33];

    const int lane = threadIdx.x & 31;
    const int ty   = threadIdx.x >> 5;
    const int blk  = blockIdx.x;

    unsigned bar_target = 0;

    if (blk < 128) {
        // ---------------- GEMM blocks: layer 0 (phase A) + layer 1 (phase B) ----
        const int ub = blk & 15, bb = blk >> 4;
        const int u0 = ub * 32, b0 = bb * 32;
        const int u  = u0 + lane;

        float bs0[4], bs1[4];
        #pragma unroll
        for (int g = 0; g < 4; g++) {
            bs0[g] = bih0[g * NH + u] + bhh0[g * NH + u];
            bs1[g] = bih1[g * NH + u] + bhh1[g * NH + u];
        }

        for (int t = 0; t <= NT; t++) {
            const int rd = t & 1, wr = rd ^ 1;

            // ---- phase A: gates0 = h0[rd] @ Whh0^T (+ one-hot LUT) -> cell 0 ----
            if (t < NT) {
                ull acc[4][2];
                #pragma unroll
                for (int g = 0; g < 4; g++) { acc[g][0] = 0ull; acc[g][1] = 0ull; }
                gemm_acc(acc, g_h0[rd], Whh0, b0, u0, NH, hs, ws2, lane, ty);

                #pragma unroll
                for (int j = 0; j < 4; j++) {
                    F2U c0, c1, c2, c3;
                    c0.u = acc[0][j >> 1]; c1.u = acc[1][j >> 1];
                    c2.u = acc[2][j >> 1]; c3.u = acc[3][j >> 1];
                    float gi = ((j & 1) ? c0.f.y : c0.f.x) + bs0[0];
                    float gf = ((j & 1) ? c1.f.y : c1.f.x) + bs0[1];
                    float gg = ((j & 1) ? c2.f.y : c2.f.x) + bs0[2];
                    float go = ((j & 1) ? c3.f.y : c3.f.x) + bs0[3];
                    int b = b0 + ty * 4 + j;
                    if (t > 0) {
                        int zp = z[b * NT + t - 1];
                        const float* lut = &g_wih0t[zp * G4 + u];
                        gi += lut[0];
                        gf += lut[NH];
                        gg += lut[2 * NH];
                        go += lut[3 * NH];
                    }
                    int idx = b * NH + u;
                    float c  = g_c0[idx];
                    float cn = sigf(gf) * c + sigf(gi) * tanhf_fast(gg);
                    g_c0[idx] = cn;
                    g_h0[wr][idx] = sigf(go) * tanhf_fast(cn);
                }
            }
            bar_target += NBLK;
            grid_barrier(bar_target);

            // ---- phase B: gates1 = h0[wr] @ Wih1^T + h1[rd] @ Whh1^T -> cell 1 ----
            if (t < NT) {
                ull acc[4][2];
                #pragma unroll
                for (int g = 0; g < 4; g++) { acc[g][0] = 0ull; acc[g][1] = 0ull; }
                gemm_acc(acc, g_h0[wr], Wih1, b0, u0, NH, hs, ws2, lane, ty);
                gemm_acc(acc, g_h1[rd], Whh1, b0, u0, NH, hs, ws2, lane, ty);

                #pragma unroll
                for (int j = 0; j < 4; j++) {
                    F2U c0, c1, c2, c3;
                    c0.u = acc[0][j >> 1]; c1.u = acc[1][j >> 1];
                    c2.u = acc[2][j >> 1]; c3.u = acc[3][j >> 1];
                    float gi = ((j & 1) ? c0.f.y : c0.f.x) + bs1[0];
                    float gf = ((j & 1) ? c1.f.y : c1.f.x) + bs1[1];
                    float gg = ((j & 1) ? c2.f.y : c2.f.x) + bs1[2];
                    float go = ((j & 1) ? c3.f.y : c3.f.x) + bs1[3];
                    int b = b0 + ty * 4 + j;
                    int idx = b * NH + u;
                    float c  = g_c1[idx];
                    float cn = sigf(gf) * c + sigf(gi) * tanhf_fast(gg);
                    g_c1[idx] = cn;
                    g_h1[wr][idx] = sigf(go) * tanhf_fast(cn);
                }
            }
            bar_target += NBLK;
            grid_barrier(bar_target);
        }
    } else {
        // ---------------- logits blocks: logits/NLL for step t-1 in phase A ----
        const int b0 = (blk - 128) * 32;
        float blv[4];
        #pragma unroll
        for (int vv = 0; vv < 4; vv++) blv[vv] = blin[vv * 32 + lane];
        int nf4[4];
        #pragma unroll
        for (int j = 0; j < 4; j++) nf4[j] = nframes[b0 + ty * 4 + j];
        float nllacc[4] = {0.f, 0.f, 0.f, 0.f};

        for (int t = 0; t <= NT; t++) {
            const int rd = t & 1;

            if (t >= 1) {
                const int s = t - 1;
                ull acc[4][2];
                #pragma unroll
                for (int g = 0; g < 4; g++) { acc[g][0] = 0ull; acc[g][1] = 0ull; }
                // logits[b][v] for v = vv*32 + lane: W row = vv*32 + u -> rowstep 32
                gemm_acc(acc, g_h1[rd], Wlin, b0, 0, 32, hs, ws2, lane, ty);

                #pragma unroll
                for (int j = 0; j < 4; j++) {
                    float lg[4];
                    #pragma unroll
                    for (int vv = 0; vv < 4; vv++) {
                        F2U cv; cv.u = acc[vv][j >> 1];
                        lg[vv] = ((j & 1) ? cv.f.y : cv.f.x) + blv[vv];
                    }
                    float m = fmaxf(fmaxf(lg[0], lg[1]), fmaxf(lg[2], lg[3]));
                    m = warp_max(m);
                    float se = 0.f;
                    #pragma unroll
                    for (int vv = 0; vv < 4; vv++) se += __expf(lg[vv] - m);
                    se = warp_sum(se);
                    float lse = m + logf(se);
                    int b = b0 + ty * 4 + j;
                    int target = z[b * NT + s];
                    float tl = 0.f;
                    #pragma unroll
                    for (int vv = 0; vv < 4; vv++)
                        if (vv * 32 + lane == target) tl = lg[vv];
                    tl = warp_sum(tl);
                    if (lane == 0 && s < nf4[j]) nllacc[j] += (lse - tl);
                }
            }
            bar_target += NBLK;
            grid_barrier(bar_target);
            // phase B: no work for logits blocks
            bar_target += NBLK;
            grid_barrier(bar_target);
        }

        if (lane == 0) {
            #pragma unroll
            for (int j = 0; j < 4; j++)
                out[b0 + ty * 4 + j] = nllacc[j] / (float)NT;
        }
    }
}

extern "C" void kernel_launch(void* const* d_in, const int* in_sizes, int n_in,
                              void* d_out, int out_size) {
    const float* Wih0 = (const float*)d_in[0];
    const float* Whh0 = (const float*)d_in[1];
    const float* bih0 = (const float*)d_in[2];
    const float* bhh0 = (const float*)d_in[3];
    const float* Wih1 = (const float*)d_in[4];
    const float* Whh1 = (const float*)d_in[5];
    const float* bih1 = (const float*)d_in[6];
    const float* bhh1 = (const float*)d_in[7];
    const float* Wlin = (const float*)d_in[8];
    const float* blin = (const float*)d_in[9];
    const int*   z    = (const int*)d_in[10];
    const int*   nf   = (const int*)d_in[11];
    float* out = (float*)d_out;

    kinit<<<256, 256>>>(Wih0);
    lstm_persistent<<<NBLK, 256>>>(Whh0, bih0, bhh0, Wih1, Whh1, bih1, bhh1,
                                   Wlin, blin, z, nf, out);
}

// round 3
// speedup vs baseline: 1.4559x; 1.4559x over previous
#include <cuda_runtime.h>
#include <math.h>

constexpr int NB  = 256;    // batch
constexpr int NT  = 800;    // time steps
constexpr int NH  = 512;    // hidden
constexpr int ND  = 128;    // input dim (= vocab)
constexpr int G4  = 2048;   // 4*NH gate rows
constexpr int NBLK = 136;   // 128 GEMM blocks + 8 logits blocks

typedef unsigned long long ull;

// ---- persistent device scratch (16-B aligned for cp.async) ----
__device__ __align__(16) float g_h0d[2][NH * NB * 2];  // [u][b dup]
__device__ __align__(16) float g_h1d[2][NH * NB * 2];
__device__ float g_c0[NH * NB];                        // [u][b]
__device__ float g_c1[NH * NB];
__device__ __align__(16) float g_w0p[NH * G4];         // [k][permuted 2048]
__device__ __align__(16) float g_w1p[2 * NH * G4];     // [k 0..1023][permuted 2048]
__device__ __align__(16) float g_wlt[NH * ND];         // [k][v]
__device__ float g_lut[ND * G4];                       // [din][gate rows]
__device__ float g_bs0[G4], g_bs1[G4];
__device__ volatile unsigned g_bar;

__device__ __forceinline__ float sigf(float x) { return 1.0f / (1.0f + __expf(-x)); }
__device__ __forceinline__ float tanhf_fast(float x) {
    x = fminf(fmaxf(x, -15.0f), 15.0f);
    float e = __expf(2.0f * x);
    return (e - 1.0f) / (e + 1.0f);
}
__device__ __forceinline__ float warp_max(float v) {
    #pragma unroll
    for (int o = 16; o; o >>= 1) v = fmaxf(v, __shfl_xor_sync(0xffffffffu, v, o));
    return v;
}
__device__ __forceinline__ float warp_sum(float v) {
    #pragma unroll
    for (int o = 16; o; o >>= 1) v += __shfl_xor_sync(0xffffffffu, v, o);
    return v;
}
__device__ __forceinline__ unsigned s2u(const void* p) {
    return (unsigned)__cvta_generic_to_shared(p);
}
#define CP16(d, s) asm volatile("cp.async.cg.shared.global [%0], [%1], 16;" :: "r"(d), "l"(s))
#define FMA2(a, w, h) asm("fma.rn.f32x2 %0, %1, %2, %0;" : "+l"(a) : "l"(w), "l"(h))

// ---- init: permute/transpose weights, zero state ----
__global__ void kinit(const float* __restrict__ Wih0, const float* __restrict__ Whh0,
                      const float* __restrict__ bih0, const float* __restrict__ bhh0,
                      const float* __restrict__ Wih1, const float* __restrict__ Whh1,
                      const float* __restrict__ bih1, const float* __restrict__ bhh1,
                      const float* __restrict__ Wlin) {
    int i0 = blockIdx.x * blockDim.x + threadIdx.x;
    int stride = gridDim.x * blockDim.x;
    if (i0 == 0) g_bar = 0;
    // permuted col c -> original gate row: ut = c>>7, r = c&127, g = r>>5, uu = r&31
    for (int o = i0; o < NH * G4; o += stride) {
        int k = o >> 11, c = o & 2047;
        int ut = c >> 7, r = c & 127, g = r >> 5, uu = r & 31;
        int row = g * NH + ut * 32 + uu;
        g_w0p[o] = Whh0[row * NH + k];
    }
    for (int o = i0; o < 2 * NH * G4; o += stride) {
        int k = o >> 11, c = o & 2047;
        int ut = c >> 7, r = c & 127, g = r >> 5, uu = r & 31;
        int row = g * NH + ut * 32 + uu;
        g_w1p[o] = (k < NH) ? Wih1[row * NH + k] : Whh1[row * NH + (k - NH)];
    }
    for (int o = i0; o < NH * ND; o += stride) {
        int k = o >> 7, v = o & 127;
        g_wlt[o] = Wlin[v * NH + k];
    }
    for (int o = i0; o < ND * G4; o += stride) {
        int d = o >> 11, r = o & 2047;
        g_lut[o] = Wih0[r * ND + d];
    }
    for (int o = i0; o < G4; o += stride) {
        g_bs0[o] = bih0[o] + bhh0[o];
        g_bs1[o] = bih1[o] + bhh1[o];
    }
    for (int o = i0; o < NH * NB; o += stride) { g_c0[o] = 0.f; g_c1[o] = 0.f; }
    for (int o = i0; o < NH * NB * 2; o += stride) {
        g_h0d[0][o] = 0.f; g_h0d[1][o] = 0.f;
        g_h1d[0][o] = 0.f; g_h1d[1][o] = 0.f;
    }
}

// ---- grid barrier (all NBLK blocks co-resident) ----
__device__ __forceinline__ void grid_barrier(unsigned target) {
    __threadfence();
    __syncthreads();
    if (threadIdx.x == 0) {
        atomicAdd((unsigned*)&g_bar, 1u);
        while (g_bar < target) { __nanosleep(32); }
    }
    __syncthreads();
    __threadfence();
}

// ---- chunk loader: 32 k-rows of w (128 cols) + h-dup (32 b) into smem ----
__device__ __forceinline__ void issue_chunk(
    const float* __restrict__ wrow,  // wsrc + kk*wcols
    int wcols, int u0,
    const float* __restrict__ arow,  // act + kk*512 + b0*2
    float* wb, float* hb, int tid)
{
    #pragma unroll
    for (int i = 0; i < 4; i++) {
        int lin = tid + i * 256;
        int row = lin >> 5, c = lin & 31;
        CP16(s2u(wb + row * 128 + c * 4), wrow + (size_t)row * wcols + u0 + c * 4);
    }
    #pragma unroll
    for (int i = 0; i < 2; i++) {
        int lin = tid + i * 256;
        int row = lin >> 4, c = lin & 15;
        CP16(s2u(hb + row * 64 + c * 4), arow + (size_t)row * (NB * 2) + c * 4);
    }
    asm volatile("cp.async.commit_group;" ::: "memory");
}

// ---- compute 32 k: 3 x LDS.128 + 8 x FFMA2 per thread per k ----
__device__ __forceinline__ void compute_chunk(
    ull acc[2][4], const float* wb, const float* hb, int wo, int ho)
{
    #pragma unroll 16
    for (int k = 0; k < 32; k++) {
        ulonglong2 w2 = *(const ulonglong2*)(wb + k * 128 + wo);
        ulonglong2 hA = *(const ulonglong2*)(hb + k * 64 + ho);
        ulonglong2 hB = *(const ulonglong2*)(hb + k * 64 + ho + 4);
        FMA2(acc[0][0], w2.x, hA.x); FMA2(acc[1][0], w2.y, hA.x);
        FMA2(acc[0][1], w2.x, hA.y); FMA2(acc[1][1], w2.y, hA.y);
        FMA2(acc[0][2], w2.x, hB.x); FMA2(acc[1][2], w2.y, hB.x);
        FMA2(acc[0][3], w2.x, hB.y); FMA2(acc[1][3], w2.y, hB.y);
    }
}

// ---- one K=512 segment: 16 chunks, double-buffered cp.async ----
__device__ __forceinline__ void gemm_seg(
    ull acc[2][4], const float* __restrict__ wsrc, int wcols, int u0,
    const float* __restrict__ act, int b0,
    float* wbuf, float* hbuf, int tid, int wo, int ho)
{
    issue_chunk(wsrc, wcols, u0, act + b0 * 2, wbuf, hbuf, tid);
    for (int ch = 0; ch < 16; ch++) {
        int buf = ch & 1;
        if (ch + 1 < 16) {
            issue_chunk(wsrc + (size_t)(ch + 1) * 32 * wcols, wcols, u0,
                        act + (size_t)(ch + 1) * 32 * (NB * 2) + b0 * 2,
                        wbuf + (buf ^ 1) * 4096, hbuf + (buf ^ 1) * 2048, tid);
            asm volatile("cp.async.wait_group 1;" ::: "memory");
        } else {
            asm volatile("cp.async.wait_group 0;" ::: "memory");
        }
        __syncthreads();
        compute_chunk(acc, wbuf + buf * 4096, hbuf + buf * 2048, wo, ho);
        __syncthreads();
    }
}

// ---- persistent kernel ----
__global__ __launch_bounds__(256) void lstm_persistent(
    const float* __restrict__ blin,
    const int* __restrict__ z, const int* __restrict__ nframes,
    float* __restrict__ out)
{
    __shared__ __align__(16) unsigned char smraw[49152];
    float* wbuf = (float*)smraw;            // 2 x [32][128] = 32 KB
    float* hbuf = (float*)(smraw + 32768);  // 2 x [32][64]  = 16 KB
    float* gbuf = (float*)smraw;            // [128][33] fp32, aliased (post-GEMM)

    const int tid  = threadIdx.x;
    const int lane = tid & 31;
    const int wid  = tid >> 5;
    const int uw = wid >> 1, bw = wid & 1;
    const int ug = lane & 7, bg = lane >> 3;
    const int wo = uw * 32 + ug * 4;           // w float offset in 128-col row
    const int ho = (bw * 16 + bg * 4) * 2;     // h-dup float offset in 64-col row
    const int r0 = uw * 32 + ug * 4;           // block-local gate rows
    const int cb = bw * 16 + bg * 4;           // block-local batch cols
    const int blk = blockIdx.x;

    unsigned bar_target = 0;

    if (blk < 128) {
        // ---------------- GEMM blocks ----------------
        const int ut = blk >> 3;        // 0..15: unit tile (32 units, all 4 gates)
        const int b0 = (blk & 7) * 32;  // batch tile

        // cell-phase thread mapping
        const int bcl = tid & 31;            // local batch
        const int uu0 = (tid >> 5) * 4;      // 4 units per thread
        const int gb  = b0 + bcl;            // global batch

        for (int t = 0; t <= NT; t++) {
            const int rd = t & 1, wr = rd ^ 1;

            // ===== phase A: layer 0 =====
            if (t < NT) {
                ull acc[2][4];
                #pragma unroll
                for (int p = 0; p < 2; p++)
                    #pragma unroll
                    for (int j = 0; j < 4; j++) acc[p][j] = 0ull;
                gemm_seg(acc, g_w0p, G4, ut * 128, g_h0d[rd], b0, wbuf, hbuf, tid, wo, ho);

                // exchange: accs -> gbuf[row][col], pitch 33
                #pragma unroll
                for (int p = 0; p < 2; p++) {
                    #pragma unroll
                    for (int j = 0; j < 4; j++) {
                        float2 v = *(float2*)&acc[p][j];
                        gbuf[(r0 + 2 * p) * 33 + cb + j]     = v.x;
                        gbuf[(r0 + 2 * p + 1) * 33 + cb + j] = v.y;
                    }
                }
                __syncthreads();

                // cell 0 update
                int zp = 0;
                const float* lut = g_lut;
                if (t > 0) { zp = z[gb * NT + t - 1]; lut = g_lut + zp * G4; }
                #pragma unroll
                for (int q = 0; q < 4; q++) {
                    int uu = uu0 + q;
                    int urow = ut * 32 + uu;   // global unit 0..511
                    float gi = gbuf[(uu) * 33 + bcl]            + g_bs0[urow];
                    float gf = gbuf[(32 + uu) * 33 + bcl]       + g_bs0[NH + urow];
                    float gg = gbuf[(64 + uu) * 33 + bcl]       + g_bs0[2 * NH + urow];
                    float go = gbuf[(96 + uu) * 33 + bcl]       + g_bs0[3 * NH + urow];
                    if (t > 0) {
                        gi += lut[urow];
                        gf += lut[NH + urow];
                        gg += lut[2 * NH + urow];
                        go += lut[3 * NH + urow];
                    }
                    int cidx = urow * NB + gb;
                    float c  = g_c0[cidx];
                    float cn = sigf(gf) * c + sigf(gi) * tanhf_fast(gg);
                    g_c0[cidx] = cn;
                    float hn = sigf(go) * tanhf_fast(cn);
                    g_h0d[wr][urow * (NB * 2) + gb * 2]     = hn;
                    g_h0d[wr][urow * (NB * 2) + gb * 2 + 1] = hn;
                }
            }
            bar_target += NBLK;
            grid_barrier(bar_target);

            // ===== phase B: layer 1 (K = 1024) =====
            if (t < NT) {
                ull acc[2][4];
                #pragma unroll
                for (int p = 0; p < 2; p++)
                    #pragma unroll
                    for (int j = 0; j < 4; j++) acc[p][j] = 0ull;
                gemm_seg(acc, g_w1p, G4, ut * 128, g_h0d[wr], b0, wbuf, hbuf, tid, wo, ho);
                gemm_seg(acc, g_w1p + (size_t)NH * G4, G4, ut * 128, g_h1d[rd], b0, wbuf, hbuf, tid, wo, ho);

                #pragma unroll
                for (int p = 0; p < 2; p++) {
                    #pragma unroll
                    for (int j = 0; j < 4; j++) {
                        float2 v = *(float2*)&acc[p][j];
                        gbuf[(r0 + 2 * p) * 33 + cb + j]     = v.x;
                        gbuf[(r0 + 2 * p + 1) * 33 + cb + j] = v.y;
                    }
                }
                __syncthreads();

                #pragma unroll
                for (int q = 0; q < 4; q++) {
                    int uu = uu0 + q;
                    int urow = ut * 32 + uu;
                    float gi = gbuf[(uu) * 33 + bcl]      + g_bs1[urow];
                    float gf = gbuf[(32 + uu) * 33 + bcl] + g_bs1[NH + urow];
                    float gg = gbuf[(64 + uu) * 33 + bcl] + g_bs1[2 * NH + urow];
                    float go = gbuf[(96 + uu) * 33 + bcl] + g_bs1[3 * NH + urow];
                    int cidx = urow * NB + gb;
                    float c  = g_c1[cidx];
                    float cn = sigf(gf) * c + sigf(gi) * tanhf_fast(gg);
                    g_c1[cidx] = cn;
                    float hn = sigf(go) * tanhf_fast(cn);
                    g_h1d[wr][urow * (NB * 2) + gb * 2]     = hn;
                    g_h1d[wr][urow * (NB * 2) + gb * 2 + 1] = hn;
                }
            }
            bar_target += NBLK;
            grid_barrier(bar_target);
        }
    } else {
        // ---------------- logits blocks: NLL for step t-1 during phase A ----------------
        const int b0 = (blk - 128) * 32;
        float nll[4];
        int nf4[4];
        #pragma unroll
        for (int bb = 0; bb < 4; bb++) {
            nll[bb] = 0.f;
            nf4[bb] = nframes[b0 + wid * 4 + bb];
        }

        for (int t = 0; t <= NT; t++) {
            const int rd = t & 1;
            if (t >= 1) {
                const int s = t - 1;
                ull acc[2][4];
                #pragma unroll
                for (int p = 0; p < 2; p++)
                    #pragma unroll
                    for (int j = 0; j < 4; j++) acc[p][j] = 0ull;
                gemm_seg(acc, g_wlt, ND, 0, g_h1d[rd], b0, wbuf, hbuf, tid, wo, ho);

                // store logits (+bias) to gbuf[v][b]
                #pragma unroll
                for (int p = 0; p < 2; p++) {
                    #pragma unroll
                    for (int j = 0; j < 4; j++) {
                        float2 v = *(float2*)&acc[p][j];
                        gbuf[(r0 + 2 * p) * 33 + cb + j]     = v.x + blin[r0 + 2 * p];
                        gbuf[(r0 + 2 * p + 1) * 33 + cb + j] = v.y + blin[r0 + 2 * p + 1];
                    }
                }
                __syncthreads();

                // softmax + NLL: warp handles 4 batch rows
                #pragma unroll
                for (int bb = 0; bb < 4; bb++) {
                    int bl = wid * 4 + bb;
                    float lg[4];
                    #pragma unroll
                    for (int j = 0; j < 4; j++)
                        lg[j] = gbuf[(lane + 32 * j) * 33 + bl];
                    float m = fmaxf(fmaxf(lg[0], lg[1]), fmaxf(lg[2], lg[3]));
                    m = warp_max(m);
                    float se = 0.f;
                    #pragma unroll
                    for (int j = 0; j < 4; j++) se += __expf(lg[j] - m);
                    se = warp_sum(se);
                    float lse = m + logf(se);
                    int tgt = z[(b0 + bl) * NT + s];
                    float tl = 0.f;
                    #pragma unroll
                    for (int j = 0; j < 4; j++)
                        if (lane + 32 * j == tgt) tl = lg[j];
                    tl = warp_sum(tl);
                    if (s < nf4[bb]) nll[bb] += (lse - tl);
                }
                __syncthreads();
            }
            bar_target += NBLK;
            grid_barrier(bar_target);
            bar_target += NBLK;
            grid_barrier(bar_target);
        }

        if (lane == 0) {
            #pragma unroll
            for (int bb = 0; bb < 4; bb++)
                out[b0 + wid * 4 + bb] = nll[bb] * (1.0f / (float)NT);
        }
    }
}

extern "C" void kernel_launch(void* const* d_in, const int* in_sizes, int n_in,
                              void* d_out, int out_size) {
    const float* Wih0 = (const float*)d_in[0];
    const float* Whh0 = (const float*)d_in[1];
    const float* bih0 = (const float*)d_in[2];
    const float* bhh0 = (const float*)d_in[3];
    const float* Wih1 = (const float*)d_in[4];
    const float* Whh1 = (const float*)d_in[5];
    const float* bih1 = (const float*)d_in[6];
    const float* bhh1 = (const float*)d_in[7];
    const float* Wlin = (const float*)d_in[8];
    const float* blin = (const float*)d_in[9];
    const int*   z    = (const int*)d_in[10];
    const int*   nf   = (const int*)d_in[11];
    float* out = (float*)d_out;

    kinit<<<256, 256>>>(Wih0, Whh0, bih0, bhh0, Wih1, Whh1, bih1, bhh1, Wlin);
    lstm_persistent<<<NBLK, 256>>>(blin, z, nf, out);
}

// round 4
// speedup vs baseline: 1.4577x; 1.0012x over previous
#include <cuda_runtime.h>
#include <math.h>

constexpr int NB  = 256;    // batch
constexpr int NT  = 800;    // time steps
constexpr int NH  = 512;    // hidden
constexpr int ND  = 128;    // input dim (= vocab)
constexpr int G4  = 2048;   // 4*NH gate rows
constexpr int NBLK = 136;   // 128 GEMM blocks + 8 logits blocks

typedef unsigned long long ull;

// ---- persistent device scratch (16-B aligned for cp.async) ----
__device__ __align__(16) float g_h0d[2][NH * NB * 2];  // [u][b dup]
__device__ __align__(16) float g_h1d[2][NH * NB * 2];
__device__ float g_c0[NH * NB];                        // [u][b]
__device__ float g_c1[NH * NB];
__device__ __align__(16) float g_w0p[NH * G4];         // [k][permuted 2048]
__device__ __align__(16) float g_w1p[2 * NH * G4];     // [k 0..1023][permuted 2048]
__device__ __align__(16) float g_wlt[NH * ND];         // [k][v]
__device__ float g_lut[ND * G4];                       // [din][gate rows]
__device__ float g_bs0[G4], g_bs1[G4];
__device__ volatile unsigned g_bar;

__device__ __forceinline__ float sigf(float x) { return 1.0f / (1.0f + __expf(-x)); }
__device__ __forceinline__ float tanhf_fast(float x) {
    x = fminf(fmaxf(x, -15.0f), 15.0f);
    float e = __expf(2.0f * x);
    return (e - 1.0f) / (e + 1.0f);
}
__device__ __forceinline__ float warp_max(float v) {
    #pragma unroll
    for (int o = 16; o; o >>= 1) v = fmaxf(v, __shfl_xor_sync(0xffffffffu, v, o));
    return v;
}
__device__ __forceinline__ float warp_sum(float v) {
    #pragma unroll
    for (int o = 16; o; o >>= 1) v += __shfl_xor_sync(0xffffffffu, v, o);
    return v;
}
__device__ __forceinline__ unsigned s2u(const void* p) {
    return (unsigned)__cvta_generic_to_shared(p);
}
#define CP16(d, s) asm volatile("cp.async.cg.shared.global [%0], [%1], 16;" :: "r"(d), "l"(s))
#define FMA2(a, w, h) asm("fma.rn.f32x2 %0, %1, %2, %0;" : "+l"(a) : "l"(w), "l"(h))

// ---- init: permute/transpose weights, zero state ----
__global__ void kinit(const float* __restrict__ Wih0, const float* __restrict__ Whh0,
                      const float* __restrict__ bih0, const float* __restrict__ bhh0,
                      const float* __restrict__ Wih1, const float* __restrict__ Whh1,
                      const float* __restrict__ bih1, const float* __restrict__ bhh1,
                      const float* __restrict__ Wlin) {
    int i0 = blockIdx.x * blockDim.x + threadIdx.x;
    int stride = gridDim.x * blockDim.x;
    if (i0 == 0) g_bar = 0;
    // permuted col c -> original gate row: ut = c>>7, r = c&127, g = r>>5, uu = r&31
    for (int o = i0; o < NH * G4; o += stride) {
        int k = o >> 11, c = o & 2047;
        int ut = c >> 7, r = c & 127, g = r >> 5, uu = r & 31;
        int row = g * NH + ut * 32 + uu;
        g_w0p[o] = Whh0[row * NH + k];
    }
    for (int o = i0; o < 2 * NH * G4; o += stride) {
        int k = o >> 11, c = o & 2047;
        int ut = c >> 7, r = c & 127, g = r >> 5, uu = r & 31;
        int row = g * NH + ut * 32 + uu;
        g_w1p[o] = (k < NH) ? Wih1[row * NH + k] : Whh1[row * NH + (k - NH)];
    }
    for (int o = i0; o < NH * ND; o += stride) {
        int k = o >> 7, v = o & 127;
        g_wlt[o] = Wlin[v * NH + k];
    }
    for (int o = i0; o < ND * G4; o += stride) {
        int d = o >> 11, r = o & 2047;
        g_lut[o] = Wih0[r * ND + d];
    }
    for (int o = i0; o < G4; o += stride) {
        g_bs0[o] = bih0[o] + bhh0[o];
        g_bs1[o] = bih1[o] + bhh1[o];
    }
    for (int o = i0; o < NH * NB; o += stride) { g_c0[o] = 0.f; g_c1[o] = 0.f; }
    for (int o = i0; o < NH * NB * 2; o += stride) {
        g_h0d[0][o] = 0.f; g_h0d[1][o] = 0.f;
        g_h1d[0][o] = 0.f; g_h1d[1][o] = 0.f;
    }
}

// ---- grid barrier (all NBLK blocks co-resident) ----
__device__ __forceinline__ void grid_barrier(unsigned target) {
    __threadfence();
    __syncthreads();
    if (threadIdx.x == 0) {
        atomicAdd((unsigned*)&g_bar, 1u);
        while (g_bar < target) { __nanosleep(32); }
    }
    __syncthreads();
    __threadfence();
}

// ---- chunk loader: 32 k-rows of w (128 cols) + h-dup (32 b) into smem ----
__device__ __forceinline__ void issue_chunk(
    const float* __restrict__ wrow,  // wsrc + kk*wcols
    int wcols, int u0,
    const float* __restrict__ arow,  // act + kk*512 + b0*2
    float* wb, float* hb, int tid)
{
    #pragma unroll
    for (int i = 0; i < 4; i++) {
        int lin = tid + i * 256;
        int row = lin >> 5, c = lin & 31;
        CP16(s2u(wb + row * 128 + c * 4), wrow + (size_t)row * wcols + u0 + c * 4);
    }
    #pragma unroll
    for (int i = 0; i < 2; i++) {
        int lin = tid + i * 256;
        int row = lin >> 4, c = lin & 15;
        CP16(s2u(hb + row * 64 + c * 4), arow + (size_t)row * (NB * 2) + c * 4);
    }
    asm volatile("cp.async.commit_group;" ::: "memory");
}

// ---- compute 32 k: 3 x LDS.128 + 8 x FFMA2 per thread per k ----
__device__ __forceinline__ void compute_chunk(
    ull acc[2][4], const float* wb, const float* hb, int wo, int ho)
{
    #pragma unroll 16
    for (int k = 0; k < 32; k++) {
        ulonglong2 w2 = *(const ulonglong2*)(wb + k * 128 + wo);
        ulonglong2 hA = *(const ulonglong2*)(hb + k * 64 + ho);
        ulonglong2 hB = *(const ulonglong2*)(hb + k * 64 + ho + 4);
        FMA2(acc[0][0], w2.x, hA.x); FMA2(acc[1][0], w2.y, hA.x);
        FMA2(acc[0][1], w2.x, hA.y); FMA2(acc[1][1], w2.y, hA.y);
        FMA2(acc[0][2], w2.x, hB.x); FMA2(acc[1][2], w2.y, hB.x);
        FMA2(acc[0][3], w2.x, hB.y); FMA2(acc[1][3], w2.y, hB.y);
    }
}

// ---- one K=512 segment: 16 chunks, double-buffered cp.async ----
__device__ __forceinline__ void gemm_seg(
    ull acc[2][4], const float* __restrict__ wsrc, int wcols, int u0,
    const float* __restrict__ act, int b0,
    float* wbuf, float* hbuf, int tid, int wo, int ho)
{
    issue_chunk(wsrc, wcols, u0, act + b0 * 2, wbuf, hbuf, tid);
    for (int ch = 0; ch < 16; ch++) {
        int buf = ch & 1;
        if (ch + 1 < 16) {
            issue_chunk(wsrc + (size_t)(ch + 1) * 32 * wcols, wcols, u0,
                        act + (size_t)(ch + 1) * 32 * (NB * 2) + b0 * 2,
                        wbuf + (buf ^ 1) * 4096, hbuf + (buf ^ 1) * 2048, tid);
            asm volatile("cp.async.wait_group 1;" ::: "memory");
        } else {
            asm volatile("cp.async.wait_group 0;" ::: "memory");
        }
        __syncthreads();
        compute_chunk(acc, wbuf + buf * 4096, hbuf + buf * 2048, wo, ho);
        __syncthreads();
    }
}

// ---- persistent kernel ----
__global__ __launch_bounds__(256) void lstm_persistent(
    const float* __restrict__ blin,
    const int* __restrict__ z, const int* __restrict__ nframes,
    float* __restrict__ out)
{
    __shared__ __align__(16) unsigned char smraw[49152];
    float* wbuf = (float*)smraw;            // 2 x [32][128] = 32 KB
    float* hbuf = (float*)(smraw + 32768);  // 2 x [32][64]  = 16 KB
    float* gbuf = (float*)smraw;            // [128][33] fp32, aliased (post-GEMM)

    const int tid  = threadIdx.x;
    const int lane = tid & 31;
    const int wid  = tid >> 5;
    const int uw = wid >> 1, bw = wid & 1;
    const int ug = lane & 7, bg = lane >> 3;
    const int wo = uw * 32 + ug * 4;           // w float offset in 128-col row
    const int ho = (bw * 16 + bg * 4) * 2;     // h-dup float offset in 64-col row
    const int r0 = uw * 32 + ug * 4;           // block-local gate rows
    const int cb = bw * 16 + bg * 4;           // block-local batch cols
    const int blk = blockIdx.x;

    unsigned bar_target = 0;

    if (blk < 128) {
        // ---------------- GEMM blocks ----------------
        const int ut = blk >> 3;        // 0..15: unit tile (32 units, all 4 gates)
        const int b0 = (blk & 7) * 32;  // batch tile

        // cell-phase thread mapping
        const int bcl = tid & 31;            // local batch
        const int uu0 = (tid >> 5) * 4;      // 4 units per thread
        const int gb  = b0 + bcl;            // global batch

        for (int t = 0; t <= NT; t++) {
            const int rd = t & 1, wr = rd ^ 1;

            // ===== phase A: layer 0 =====
            if (t < NT) {
                ull acc[2][4];
                #pragma unroll
                for (int p = 0; p < 2; p++)
                    #pragma unroll
                    for (int j = 0; j < 4; j++) acc[p][j] = 0ull;
                gemm_seg(acc, g_w0p, G4, ut * 128, g_h0d[rd], b0, wbuf, hbuf, tid, wo, ho);

                // exchange: accs -> gbuf[row][col], pitch 33
                #pragma unroll
                for (int p = 0; p < 2; p++) {
                    #pragma unroll
                    for (int j = 0; j < 4; j++) {
                        float2 v = *(float2*)&acc[p][j];
                        gbuf[(r0 + 2 * p) * 33 + cb + j]     = v.x;
                        gbuf[(r0 + 2 * p + 1) * 33 + cb + j] = v.y;
                    }
                }
                __syncthreads();

                // cell 0 update
                int zp = 0;
                const float* lut = g_lut;
                if (t > 0) { zp = z[gb * NT + t - 1]; lut = g_lut + zp * G4; }
                #pragma unroll
                for (int q = 0; q < 4; q++) {
                    int uu = uu0 + q;
                    int urow = ut * 32 + uu;   // global unit 0..511
                    float gi = gbuf[(uu) * 33 + bcl]            + g_bs0[urow];
                    float gf = gbuf[(32 + uu) * 33 + bcl]       + g_bs0[NH + urow];
                    float gg = gbuf[(64 + uu) * 33 + bcl]       + g_bs0[2 * NH + urow];
                    float go = gbuf[(96 + uu) * 33 + bcl]       + g_bs0[3 * NH + urow];
                    if (t > 0) {
                        gi += lut[urow];
                        gf += lut[NH + urow];
                        gg += lut[2 * NH + urow];
                        go += lut[3 * NH + urow];
                    }
                    int cidx = urow * NB + gb;
                    float c  = g_c0[cidx];
                    float cn = sigf(gf) * c + sigf(gi) * tanhf_fast(gg);
                    g_c0[cidx] = cn;
                    float hn = sigf(go) * tanhf_fast(cn);
                    g_h0d[wr][urow * (NB * 2) + gb * 2]     = hn;
                    g_h0d[wr][urow * (NB * 2) + gb * 2 + 1] = hn;
                }
            }
            bar_target += NBLK;
            grid_barrier(bar_target);

            // ===== phase B: layer 1 (K = 1024) =====
            if (t < NT) {
                ull acc[2][4];
                #pragma unroll
                for (int p = 0; p < 2; p++)
                    #pragma unroll
                    for (int j = 0; j < 4; j++) acc[p][j] = 0ull;
                gemm_seg(acc, g_w1p, G4, ut * 128, g_h0d[wr], b0, wbuf, hbuf, tid, wo, ho);
                gemm_seg(acc, g_w1p + (size_t)NH * G4, G4, ut * 128, g_h1d[rd], b0, wbuf, hbuf, tid, wo, ho);

                #pragma unroll
                for (int p = 0; p < 2; p++) {
                    #pragma unroll
                    for (int j = 0; j < 4; j++) {
                        float2 v = *(float2*)&acc[p][j];
                        gbuf[(r0 + 2 * p) * 33 + cb + j]     = v.x;
                        gbuf[(r0 + 2 * p + 1) * 33 + cb + j] = v.y;
                    }
                }
                __syncthreads();

                #pragma unroll
                for (int q = 0; q < 4; q++) {
                    int uu = uu0 + q;
                    int urow = ut * 32 + uu;
                    float gi = gbuf[(uu) * 33 + bcl]      + g_bs1[urow];
                    float gf = gbuf[(32 + uu) * 33 + bcl] + g_bs1[NH + urow];
                    float gg = gbuf[(64 + uu) * 33 + bcl] + g_bs1[2 * NH + urow];
                    float go = gbuf[(96 + uu) * 33 + bcl] + g_bs1[3 * NH + urow];
                    int cidx = urow * NB + gb;
                    float c  = g_c1[cidx];
                    float cn = sigf(gf) * c + sigf(gi) * tanhf_fast(gg);
                    g_c1[cidx] = cn;
                    float hn = sigf(go) * tanhf_fast(cn);
                    g_h1d[wr][urow * (NB * 2) + gb * 2]     = hn;
                    g_h1d[wr][urow * (NB * 2) + gb * 2 + 1] = hn;
                }
            }
            bar_target += NBLK;
            grid_barrier(bar_target);
        }
    } else {
        // ---------------- logits blocks: NLL for step t-1 during phase A ----------------
        const int b0 = (blk - 128) * 32;
        float nll[4];
        int nf4[4];
        #pragma unroll
        for (int bb = 0; bb < 4; bb++) {
            nll[bb] = 0.f;
            nf4[bb] = nframes[b0 + wid * 4 + bb];
        }

        for (int t = 0; t <= NT; t++) {
            const int rd = t & 1;
            if (t >= 1) {
                const int s = t - 1;
                ull acc[2][4];
                #pragma unroll
                for (int p = 0; p < 2; p++)
                    #pragma unroll
                    for (int j = 0; j < 4; j++) acc[p][j] = 0ull;
                gemm_seg(acc, g_wlt, ND, 0, g_h1d[rd], b0, wbuf, hbuf, tid, wo, ho);

                // store logits (+bias) to gbuf[v][b]
                #pragma unroll
                for (int p = 0; p < 2; p++) {
                    #pragma unroll
                    for (int j = 0; j < 4; j++) {
                        float2 v = *(float2*)&acc[p][j];
                        gbuf[(r0 + 2 * p) * 33 + cb + j]     = v.x + blin[r0 + 2 * p];
                        gbuf[(r0 + 2 * p + 1) * 33 + cb + j] = v.y + blin[r0 + 2 * p + 1];
                    }
                }
                __syncthreads();

                // softmax + NLL: warp handles 4 batch rows
                #pragma unroll
                for (int bb = 0; bb < 4; bb++) {
                    int bl = wid * 4 + bb;
                    float lg[4];
                    #pragma unroll
                    for (int j = 0; j < 4; j++)
                        lg[j] = gbuf[(lane + 32 * j) * 33 + bl];
                    float m = fmaxf(fmaxf(lg[0], lg[1]), fmaxf(lg[2], lg[3]));
                    m = warp_max(m);
                    float se = 0.f;
                    #pragma unroll
                    for (int j = 0; j < 4; j++) se += __expf(lg[j] - m);
                    se = warp_sum(se);
                    float lse = m + logf(se);
                    int tgt = z[(b0 + bl) * NT + s];
                    float tl = 0.f;
                    #pragma unroll
                    for (int j = 0; j < 4; j++)
                        if (lane + 32 * j == tgt) tl = lg[j];
                    tl = warp_sum(tl);
                    if (s < nf4[bb]) nll[bb] += (lse - tl);
                }
                __syncthreads();
            }
            bar_target += NBLK;
            grid_barrier(bar_target);
            bar_target += NBLK;
            grid_barrier(bar_target);
        }

        if (lane == 0) {
            #pragma unroll
            for (int bb = 0; bb < 4; bb++)
                out[b0 + wid * 4 + bb] = nll[bb] * (1.0f / (float)NT);
        }
    }
}

extern "C" void kernel_launch(void* const* d_in, const int* in_sizes, int n_in,
                              void* d_out, int out_size) {
    const float* Wih0 = (const float*)d_in[0];
    const float* Whh0 = (const float*)d_in[1];
    const float* bih0 = (const float*)d_in[2];
    const float* bhh0 = (const float*)d_in[3];
    const float* Wih1 = (const float*)d_in[4];
    const float* Whh1 = (const float*)d_in[5];
    const float* bih1 = (const float*)d_in[6];
    const float* bhh1 = (const float*)d_in[7];
    const float* Wlin = (const float*)d_in[8];
    const float* blin = (const float*)d_in[9];
    const int*   z    = (const int*)d_in[10];
    const int*   nf   = (const int*)d_in[11];
    float* out = (float*)d_out;

    kinit<<<256, 256>>>(Wih0, Whh0, bih0, bhh0, Wih1, Whh1, bih1, bhh1, Wlin);
    lstm_persistent<<<NBLK, 256>>>(blin, z, nf, out);
}

// round 5
// speedup vs baseline: 1.8616x; 1.2771x over previous
#include <cuda_runtime.h>
#include <math.h>

constexpr int NB  = 256;
constexpr int NT  = 800;
constexpr int NH  = 512;
constexpr int ND  = 128;
constexpr int NBLK = 136;      // 128 GEMM + 8 logits blocks
constexpr int NS   = 4;        // pipeline stages
constexpr int CHB_W = 16384;   // 32k x 128 cols x 4B
constexpr int CHB_H = 8192;    // 32k x 32b-dup x 8B
constexpr int STAGE = CHB_W + CHB_H;
constexpr int SMEM_DYN = NS * STAGE + 64;   // 98368

typedef unsigned long long ull;

// ---- persistent device scratch ----
__device__ __align__(16) float g_w0p[16 * 16 * 32 * 128];   // [strip][ch][k][col] 4MB
__device__ __align__(16) float g_w1p[16 * 32 * 32 * 128];   // 8MB
__device__ __align__(16) float g_wlt[16 * 32 * 128];        // [ch][k][v] 256KB
__device__ __align__(16) float g_h0d[2][8 * 16 * 32 * 64];  // [buf][btile][ch][k][bdup]
__device__ __align__(16) float g_h1d[2][8 * 16 * 32 * 64];
__device__ float g_c0[NH * NB], g_c1[NH * NB];              // [u][b]
__device__ float g_bs0[2048], g_bs1[2048];
__device__ volatile unsigned g_bar;

__device__ __forceinline__ float sigf(float x) { return 1.0f / (1.0f + __expf(-x)); }
__device__ __forceinline__ float tanhf_fast(float x) {
    x = fminf(fmaxf(x, -15.0f), 15.0f);
    float e = __expf(2.0f * x);
    return (e - 1.0f) / (e + 1.0f);
}
__device__ __forceinline__ float warp_max(float v) {
    #pragma unroll
    for (int o = 16; o; o >>= 1) v = fmaxf(v, __shfl_xor_sync(0xffffffffu, v, o));
    return v;
}
__device__ __forceinline__ float warp_sum(float v) {
    #pragma unroll
    for (int o = 16; o; o >>= 1) v += __shfl_xor_sync(0xffffffffu, v, o);
    return v;
}
#define FMA2(a, w, h) asm("fma.rn.f32x2 %0, %1, %2, %0;" : "+l"(a) : "l"(w), "l"(h))

// ---- init: pack weights into per-(strip,chunk) contiguous slabs ----
__global__ void kinit(const float* __restrict__ Whh0,
                      const float* __restrict__ bih0, const float* __restrict__ bhh0,
                      const float* __restrict__ Wih1, const float* __restrict__ Whh1,
                      const float* __restrict__ bih1, const float* __restrict__ bhh1,
                      const float* __restrict__ Wlin) {
    int i0 = blockIdx.x * blockDim.x + threadIdx.x;
    int stride = gridDim.x * blockDim.x;
    if (i0 == 0) g_bar = 0;
    // w0p: col c -> unit uu=c>>2, gate g=c&3 ; row = g*512 + s*32 + uu
    for (int off = i0; off < 16 * 65536; off += stride) {
        int s = off >> 16, r = off & 65535;
        int ch = r >> 12, kk = (r >> 7) & 31, c = r & 127;
        int row = (c & 3) * 512 + s * 32 + (c >> 2);
        g_w0p[off] = Whh0[row * 512 + ch * 32 + kk];
    }
    for (int off = i0; off < 16 * 131072; off += stride) {
        int s = off >> 17, r = off & 131071;
        int ch = r >> 12, kk = (r >> 7) & 31, c = r & 127;
        int row = (c & 3) * 512 + s * 32 + (c >> 2);
        int k = ch * 32 + kk;
        g_w1p[off] = (k < 512) ? Wih1[row * 512 + k] : Whh1[row * 512 + k - 512];
    }
    for (int off = i0; off < 65536; off += stride) {
        int ch = off >> 12, kk = (off >> 7) & 31, v = off & 127;
        g_wlt[off] = Wlin[v * 512 + ch * 32 + kk];
    }
    for (int o = i0; o < 2048; o += stride) {
        g_bs0[o] = bih0[o] + bhh0[o];
        g_bs1[o] = bih1[o] + bhh1[o];
    }
    for (int o = i0; o < NH * NB; o += stride) { g_c0[o] = 0.f; g_c1[o] = 0.f; }
    for (int o = i0; o < 8 * 16 * 32 * 64; o += stride) {
        g_h0d[0][o] = 0.f; g_h0d[1][o] = 0.f;
        g_h1d[0][o] = 0.f; g_h1d[1][o] = 0.f;
    }
}

// ---- grid barrier ----
__device__ __forceinline__ void grid_barrier(unsigned target) {
    __threadfence();
    __syncthreads();
    if (threadIdx.x == 0) {
        atomicAdd((unsigned*)&g_bar, 1u);
        while (g_bar < target) { __nanosleep(32); }
    }
    __syncthreads();
    __threadfence();
}

// ---- bulk-copy chunk issue (single thread) ----
__device__ __forceinline__ void issue_chunk(char* sm, unsigned mbar, int i,
                                            const float* wsrc, const float* hsrc) {
    if (threadIdx.x == 0) {
        int slot = i & (NS - 1);
        unsigned mb = mbar + slot * 8;
        unsigned wd = (unsigned)__cvta_generic_to_shared(sm + slot * STAGE);
        unsigned hd = wd + CHB_W;
        asm volatile("mbarrier.arrive.expect_tx.shared.b64 _, [%0], %1;"
                     :: "r"(mb), "r"((unsigned)STAGE) : "memory");
        asm volatile("cp.async.bulk.shared::cluster.global.mbarrier::complete_tx::bytes [%0], [%1], %2, [%3];"
                     :: "r"(wd), "l"(wsrc), "r"((unsigned)CHB_W), "r"(mb) : "memory");
        asm volatile("cp.async.bulk.shared::cluster.global.mbarrier::complete_tx::bytes [%0], [%1], %2, [%3];"
                     :: "r"(hd), "l"(hsrc), "r"((unsigned)CHB_H), "r"(mb) : "memory");
    }
}

__device__ __forceinline__ void wait_chunk(unsigned mbar, int i) {
    unsigned mb = mbar + (i & (NS - 1)) * 8;
    unsigned par = (unsigned)(i >> 2) & 1u;
    unsigned done;
    asm volatile(
        "{\n\t.reg .pred p;\n\t"
        "mbarrier.try_wait.parity.acquire.cta.shared::cta.b64 p, [%1], %2;\n\t"
        "selp.b32 %0, 1, 0, p;\n\t}"
        : "=r"(done) : "r"(mb), "r"(par) : "memory");
    if (!done) {
        asm volatile(
            "{\n\t.reg .pred P1;\n\t"
            "WL_%=:\n\t"
            "mbarrier.try_wait.parity.acquire.cta.shared::cta.b64 P1, [%0], %1, 0x989680;\n\t"
            "@P1 bra.uni WD_%=;\n\t"
            "bra.uni WL_%=;\n\t"
            "WD_%=:\n\t}"
            :: "r"(mb), "r"(par) : "memory");
    }
}

// ---- compute 16 k-columns of a chunk (this warp's k-half) ----
__device__ __forceinline__ void compute_chunk(ull acc[4][4], const char* sm, int slot,
                                              int co, int bo, int kh) {
    const float* wst = (const float*)(sm + slot * STAGE);
    const float* hst = (const float*)(sm + slot * STAGE + CHB_W);
    #pragma unroll
    for (int k2 = 0; k2 < 16; k2++) {
        int kk = kh * 16 + k2;
        ulonglong2 wA = *(const ulonglong2*)(wst + kk * 128 + co);
        ulonglong2 wB = *(const ulonglong2*)(wst + kk * 128 + co + 4);
        ulonglong2 hA = *(const ulonglong2*)(hst + kk * 64 + bo * 2);
        ulonglong2 hB = *(const ulonglong2*)(hst + kk * 64 + bo * 2 + 4);
        FMA2(acc[0][0], wA.x, hA.x); FMA2(acc[1][0], wA.y, hA.x);
        FMA2(acc[2][0], wB.x, hA.x); FMA2(acc[3][0], wB.y, hA.x);
        FMA2(acc[0][1], wA.x, hA.y); FMA2(acc[1][1], wA.y, hA.y);
        FMA2(acc[2][1], wB.x, hA.y); FMA2(acc[3][1], wB.y, hA.y);
        FMA2(acc[0][2], wA.x, hB.x); FMA2(acc[1][2], wA.y, hB.x);
        FMA2(acc[2][2], wB.x, hB.x); FMA2(acc[3][2], wB.y, hB.x);
        FMA2(acc[0][3], wA.x, hB.y); FMA2(acc[1][3], wA.y, hB.y);
        FMA2(acc[2][3], wB.x, hB.y); FMA2(acc[3][3], wB.y, hB.y);
    }
}

// ---- one GEMM segment (nch chunks), 4-deep bulk-copy pipeline ----
__device__ __forceinline__ void run_seg(ull acc[4][4], char* sm, unsigned mbar, int& ic,
                                        const float* wb, const float* hb0, const float* hb1,
                                        int nch, int hsw, int co, int bo, int kh) {
    #pragma unroll
    for (int j = 0; j < NS; j++) {
        const float* hs = (j < hsw) ? hb0 + j * 2048 : hb1 + (j - hsw) * 2048;
        issue_chunk(sm, mbar, ic + j, wb + j * 4096, hs);
    }
    for (int ch = 0; ch < nch; ch++) {
        int i = ic + ch;
        wait_chunk(mbar, i);
        compute_chunk(acc, sm, i & (NS - 1), co, bo, kh);
        __syncthreads();
        int nx = ch + NS;
        if (nx < nch) {
            const float* hs = (nx < hsw) ? hb0 + nx * 2048 : hb1 + (nx - hsw) * 2048;
            issue_chunk(sm, mbar, ic + nx, wb + nx * 4096, hs);
        }
    }
    ic += nch;
}

// ---- epilogue: accs -> gbuf[kh][col][b] (pitch 33) ----
__device__ __forceinline__ void store_gbuf(float* gbuf, ull acc[4][4],
                                           int co, int bo, int kh) {
    #pragma unroll
    for (int p = 0; p < 4; p++) {
        #pragma unroll
        for (int b = 0; b < 4; b++) {
            float2 v = *(float2*)&acc[p][b];
            gbuf[(kh * 128 + co + 2 * p) * 33 + bo + b]     = v.x;
            gbuf[(kh * 128 + co + 2 * p + 1) * 33 + bo + b] = v.y;
        }
    }
}

__global__ void __launch_bounds__(256, 1) lstm_persistent(
    const float* __restrict__ Wih0,     // [2048][128] = input LUT, natural layout
    const float* __restrict__ blin,
    const int* __restrict__ z, const int* __restrict__ nframes,
    float* __restrict__ out)
{
    extern __shared__ __align__(16) char sm[];
    float* gbuf = (float*)sm;   // 2*128*33 floats, aliased onto stage mem
    unsigned mbar = (unsigned)__cvta_generic_to_shared(sm + NS * STAGE);

    const int tid  = threadIdx.x;
    const int lane = tid & 31, wid = tid >> 5;
    const int kh = wid >> 2, wq = wid & 3;
    const int co = wq * 32 + (lane & 3) * 8;
    const int bo = (lane >> 2) * 4;
    const int blk = blockIdx.x;

    if (tid == 0) {
        #pragma unroll
        for (int s = 0; s < NS; s++)
            asm volatile("mbarrier.init.shared.b64 [%0], 1;" :: "r"(mbar + s * 8) : "memory");
    }
    __syncthreads();

    unsigned bar_t = 0;
    int ic = 0;

    if (blk < 128) {
        const int st = blk >> 3, bt = blk & 7, b0 = bt * 32;
        const int bl = tid & 31, uu4 = (tid >> 5) * 4;
        const int gb_ = b0 + bl;
        const float* w0 = g_w0p + st * 65536;
        const float* w1 = g_w1p + st * 131072;

        for (int t = 0; t <= NT; t++) {
            const int rd = t & 1, wr = rd ^ 1;

            // ===== phase A: layer 0 =====
            if (t < NT) {
                ull acc[4][4] = {};
                run_seg(acc, sm, mbar, ic, w0, g_h0d[rd] + bt * 32768, nullptr,
                        16, 16, co, bo, kh);
                store_gbuf(gbuf, acc, co, bo, kh);
                __syncthreads();

                int zp = (t > 0) ? z[gb_ * NT + t - 1] : 0;
                #pragma unroll
                for (int q = 0; q < 4; q++) {
                    int uu = uu4 + q, urow = st * 32 + uu, col = uu * 4;
                    float gi = gbuf[(col + 0) * 33 + bl] + gbuf[(128 + col + 0) * 33 + bl] + g_bs0[urow];
                    float gf = gbuf[(col + 1) * 33 + bl] + gbuf[(128 + col + 1) * 33 + bl] + g_bs0[512 + urow];
                    float gg = gbuf[(col + 2) * 33 + bl] + gbuf[(128 + col + 2) * 33 + bl] + g_bs0[1024 + urow];
                    float go = gbuf[(col + 3) * 33 + bl] + gbuf[(128 + col + 3) * 33 + bl] + g_bs0[1536 + urow];
                    if (t > 0) {
                        gi += Wih0[urow * 128 + zp];
                        gf += Wih0[(512 + urow) * 128 + zp];
                        gg += Wih0[(1024 + urow) * 128 + zp];
                        go += Wih0[(1536 + urow) * 128 + zp];
                    }
                    int cidx = urow * NB + gb_;
                    float c  = g_c0[cidx];
                    float cn = sigf(gf) * c + sigf(gi) * tanhf_fast(gg);
                    g_c0[cidx] = cn;
                    float hn = sigf(go) * tanhf_fast(cn);
                    int hoff = ((bt * 16 + (urow >> 5)) * 32 + (urow & 31)) * 64 + bl * 2;
                    *(float2*)&g_h0d[wr][hoff] = make_float2(hn, hn);
                }
            }
            bar_t += NBLK; grid_barrier(bar_t);

            // ===== phase B: layer 1 (32 chunks: h0 then h1) =====
            if (t < NT) {
                ull acc[4][4] = {};
                run_seg(acc, sm, mbar, ic, w1,
                        g_h0d[wr] + bt * 32768, g_h1d[rd] + bt * 32768,
                        32, 16, co, bo, kh);
                store_gbuf(gbuf, acc, co, bo, kh);
                __syncthreads();

                #pragma unroll
                for (int q = 0; q < 4; q++) {
                    int uu = uu4 + q, urow = st * 32 + uu, col = uu * 4;
                    float gi = gbuf[(col + 0) * 33 + bl] + gbuf[(128 + col + 0) * 33 + bl] + g_bs1[urow];
                    float gf = gbuf[(col + 1) * 33 + bl] + gbuf[(128 + col + 1) * 33 + bl] + g_bs1[512 + urow];
                    float gg = gbuf[(col + 2) * 33 + bl] + gbuf[(128 + col + 2) * 33 + bl] + g_bs1[1024 + urow];
                    float go = gbuf[(col + 3) * 33 + bl] + gbuf[(128 + col + 3) * 33 + bl] + g_bs1[1536 + urow];
                    int cidx = urow * NB + gb_;
                    float c  = g_c1[cidx];
                    float cn = sigf(gf) * c + sigf(gi) * tanhf_fast(gg);
                    g_c1[cidx] = cn;
                    float hn = sigf(go) * tanhf_fast(cn);
                    int hoff = ((bt * 16 + (urow >> 5)) * 32 + (urow & 31)) * 64 + bl * 2;
                    *(float2*)&g_h1d[wr][hoff] = make_float2(hn, hn);
                }
            }
            bar_t += NBLK; grid_barrier(bar_t);
        }
    } else {
        // ---------------- logits blocks: NLL for step t-1 in phase A ----------------
        const int bt = blk - 128, b0 = bt * 32;
        float nll[4];
        int nf4[4];
        #pragma unroll
        for (int bb = 0; bb < 4; bb++) {
            nll[bb] = 0.f;
            nf4[bb] = nframes[b0 + wid * 4 + bb];
        }

        for (int t = 0; t <= NT; t++) {
            const int rd = t & 1;
            if (t >= 1) {
                const int s_ = t - 1;
                ull acc[4][4] = {};
                run_seg(acc, sm, mbar, ic, g_wlt, g_h1d[rd] + bt * 32768, nullptr,
                        16, 16, co, bo, kh);
                store_gbuf(gbuf, acc, co, bo, kh);
                __syncthreads();

                #pragma unroll
                for (int bb = 0; bb < 4; bb++) {
                    int blr = wid * 4 + bb;
                    float lg[4];
                    #pragma unroll
                    for (int j = 0; j < 4; j++)
                        lg[j] = gbuf[(lane + 32 * j) * 33 + blr]
                              + gbuf[(128 + lane + 32 * j) * 33 + blr]
                              + blin[lane + 32 * j];
                    float m = fmaxf(fmaxf(lg[0], lg[1]), fmaxf(lg[2], lg[3]));
                    m = warp_max(m);
                    float se = 0.f;
                    #pragma unroll
                    for (int j = 0; j < 4; j++) se += __expf(lg[j] - m);
                    se = warp_sum(se);
                    float lse = m + logf(se);
                    int tgt = z[(b0 + blr) * NT + s_];
                    float tl = 0.f;
                    #pragma unroll
                    for (int j = 0; j < 4; j++)
                        if (lane + 32 * j == tgt) tl = lg[j];
                    tl = warp_sum(tl);
                    if (s_ < nf4[bb]) nll[bb] += (lse - tl);
                }
            }
            bar_t += NBLK; grid_barrier(bar_t);
            bar_t += NBLK; grid_barrier(bar_t);
        }

        if (lane == 0) {
            #pragma unroll
            for (int bb = 0; bb < 4; bb++)
                out[b0 + wid * 4 + bb] = nll[bb] * (1.0f / (float)NT);
        }
    }
}

extern "C" void kernel_launch(void* const* d_in, const int* in_sizes, int n_in,
                              void* d_out, int out_size) {
    const float* Wih0 = (const float*)d_in[0];
    const float* Whh0 = (const float*)d_in[1];
    const float* bih0 = (const float*)d_in[2];
    const float* bhh0 = (const float*)d_in[3];
    const float* Wih1 = (const float*)d_in[4];
    const float* Whh1 = (const float*)d_in[5];
    const float* bih1 = (const float*)d_in[6];
    const float* bhh1 = (const float*)d_in[7];
    const float* Wlin = (const float*)d_in[8];
    const float* blin = (const float*)d_in[9];
    const int*   z    = (const int*)d_in[10];
    const int*   nf   = (const int*)d_in[11];
    float* out = (float*)d_out;

    cudaFuncSetAttribute(lstm_persistent,
                         cudaFuncAttributeMaxDynamicSharedMemorySize, SMEM_DYN);
    kinit<<<256, 256>>>(Whh0, bih0, bhh0, Wih1, Whh1, bih1, bhh1, Wlin);
    lstm_persistent<<<NBLK, 256, SMEM_DYN>>>(Wih0, blin, z, nf, out);
}

// round 6
// speedup vs baseline: 1.8632x; 1.0008x over previous
#include <cuda_runtime.h>
#include <math.h>

constexpr int NB  = 256;
constexpr int NT  = 800;
constexpr int NH  = 512;
constexpr int ND  = 128;
constexpr int NBLK = 136;      // 128 GEMM + 8 logits blocks
constexpr int NS   = 4;        // pipeline stages
constexpr int CHB_W = 16384;   // 32k x 128 cols x 4B
constexpr int CHB_H = 8192;    // 32k x 32b-dup x 8B
constexpr int STAGE = CHB_W + CHB_H;
constexpr int SMEM_DYN = NS * STAGE + 64;   // 98368

typedef unsigned long long ull;

// ---- persistent device scratch ----
__device__ __align__(16) float g_w0p[16 * 16 * 32 * 128];   // [strip][ch][k][col] 4MB
__device__ __align__(16) float g_w1p[16 * 32 * 32 * 128];   // 8MB
__device__ __align__(16) float g_wlt[16 * 32 * 128];        // [ch][k][v] 256KB
__device__ __align__(16) float g_h0d[2][8 * 16 * 32 * 64];  // [buf][btile][ch][k][bdup]
__device__ __align__(16) float g_h1d[2][8 * 16 * 32 * 64];
__device__ float g_c0[NH * NB], g_c1[NH * NB];              // [u][b]
__device__ float g_bs0[2048], g_bs1[2048];
__device__ volatile unsigned g_bar;

__device__ __forceinline__ float sigf(float x) { return 1.0f / (1.0f + __expf(-x)); }
__device__ __forceinline__ float tanhf_fast(float x) {
    x = fminf(fmaxf(x, -15.0f), 15.0f);
    float e = __expf(2.0f * x);
    return (e - 1.0f) / (e + 1.0f);
}
__device__ __forceinline__ float warp_max(float v) {
    #pragma unroll
    for (int o = 16; o; o >>= 1) v = fmaxf(v, __shfl_xor_sync(0xffffffffu, v, o));
    return v;
}
__device__ __forceinline__ float warp_sum(float v) {
    #pragma unroll
    for (int o = 16; o; o >>= 1) v += __shfl_xor_sync(0xffffffffu, v, o);
    return v;
}
#define FMA2(a, w, h) asm("fma.rn.f32x2 %0, %1, %2, %0;" : "+l"(a) : "l"(w), "l"(h))

// ---- init: pack weights into per-(strip,chunk) contiguous slabs ----
__global__ void kinit(const float* __restrict__ Whh0,
                      const float* __restrict__ bih0, const float* __restrict__ bhh0,
                      const float* __restrict__ Wih1, const float* __restrict__ Whh1,
                      const float* __restrict__ bih1, const float* __restrict__ bhh1,
                      const float* __restrict__ Wlin) {
    int i0 = blockIdx.x * blockDim.x + threadIdx.x;
    int stride = gridDim.x * blockDim.x;
    if (i0 == 0) g_bar = 0;
    // w0p: col c -> unit uu=c>>2, gate g=c&3 ; row = g*512 + s*32 + uu
    for (int off = i0; off < 16 * 65536; off += stride) {
        int s = off >> 16, r = off & 65535;
        int ch = r >> 12, kk = (r >> 7) & 31, c = r & 127;
        int row = (c & 3) * 512 + s * 32 + (c >> 2);
        g_w0p[off] = Whh0[row * 512 + ch * 32 + kk];
    }
    for (int off = i0; off < 16 * 131072; off += stride) {
        int s = off >> 17, r = off & 131071;
        int ch = r >> 12, kk = (r >> 7) & 31, c = r & 127;
        int row = (c & 3) * 512 + s * 32 + (c >> 2);
        int k = ch * 32 + kk;
        g_w1p[off] = (k < 512) ? Wih1[row * 512 + k] : Whh1[row * 512 + k - 512];
    }
    for (int off = i0; off < 65536; off += stride) {
        int ch = off >> 12, kk = (off >> 7) & 31, v = off & 127;
        g_wlt[off] = Wlin[v * 512 + ch * 32 + kk];
    }
    for (int o = i0; o < 2048; o += stride) {
        g_bs0[o] = bih0[o] + bhh0[o];
        g_bs1[o] = bih1[o] + bhh1[o];
    }
    for (int o = i0; o < NH * NB; o += stride) { g_c0[o] = 0.f; g_c1[o] = 0.f; }
    for (int o = i0; o < 8 * 16 * 32 * 64; o += stride) {
        g_h0d[0][o] = 0.f; g_h0d[1][o] = 0.f;
        g_h1d[0][o] = 0.f; g_h1d[1][o] = 0.f;
    }
}

// ---- grid barrier ----
__device__ __forceinline__ void grid_barrier(unsigned target) {
    __threadfence();
    __syncthreads();
    if (threadIdx.x == 0) {
        atomicAdd((unsigned*)&g_bar, 1u);
        while (g_bar < target) { __nanosleep(32); }
    }
    __syncthreads();
    __threadfence();
}

// ---- bulk-copy chunk issue (single thread) ----
__device__ __forceinline__ void issue_chunk(char* sm, unsigned mbar, int i,
                                            const float* wsrc, const float* hsrc) {
    if (threadIdx.x == 0) {
        int slot = i & (NS - 1);
        unsigned mb = mbar + slot * 8;
        unsigned wd = (unsigned)__cvta_generic_to_shared(sm + slot * STAGE);
        unsigned hd = wd + CHB_W;
        asm volatile("mbarrier.arrive.expect_tx.shared.b64 _, [%0], %1;"
                     :: "r"(mb), "r"((unsigned)STAGE) : "memory");
        asm volatile("cp.async.bulk.shared::cluster.global.mbarrier::complete_tx::bytes [%0], [%1], %2, [%3];"
                     :: "r"(wd), "l"(wsrc), "r"((unsigned)CHB_W), "r"(mb) : "memory");
        asm volatile("cp.async.bulk.shared::cluster.global.mbarrier::complete_tx::bytes [%0], [%1], %2, [%3];"
                     :: "r"(hd), "l"(hsrc), "r"((unsigned)CHB_H), "r"(mb) : "memory");
    }
}

__device__ __forceinline__ void wait_chunk(unsigned mbar, int i) {
    unsigned mb = mbar + (i & (NS - 1)) * 8;
    unsigned par = (unsigned)(i >> 2) & 1u;
    unsigned done;
    asm volatile(
        "{\n\t.reg .pred p;\n\t"
        "mbarrier.try_wait.parity.acquire.cta.shared::cta.b64 p, [%1], %2;\n\t"
        "selp.b32 %0, 1, 0, p;\n\t}"
        : "=r"(done) : "r"(mb), "r"(par) : "memory");
    if (!done) {
        asm volatile(
            "{\n\t.reg .pred P1;\n\t"
            "WL_%=:\n\t"
            "mbarrier.try_wait.parity.acquire.cta.shared::cta.b64 P1, [%0], %1, 0x989680;\n\t"
            "@P1 bra.uni WD_%=;\n\t"
            "bra.uni WL_%=;\n\t"
            "WD_%=:\n\t}"
            :: "r"(mb), "r"(par) : "memory");
    }
}

// ---- compute 16 k-columns of a chunk (this warp's k-half) ----
__device__ __forceinline__ void compute_chunk(ull acc[4][4], const char* sm, int slot,
                                              int co, int bo, int kh) {
    const float* wst = (const float*)(sm + slot * STAGE);
    const float* hst = (const float*)(sm + slot * STAGE + CHB_W);
    #pragma unroll
    for (int k2 = 0; k2 < 16; k2++) {
        int kk = kh * 16 + k2;
        ulonglong2 wA = *(const ulonglong2*)(wst + kk * 128 + co);
        ulonglong2 wB = *(const ulonglong2*)(wst + kk * 128 + co + 4);
        ulonglong2 hA = *(const ulonglong2*)(hst + kk * 64 + bo * 2);
        ulonglong2 hB = *(const ulonglong2*)(hst + kk * 64 + bo * 2 + 4);
        FMA2(acc[0][0], wA.x, hA.x); FMA2(acc[1][0], wA.y, hA.x);
        FMA2(acc[2][0], wB.x, hA.x); FMA2(acc[3][0], wB.y, hA.x);
        FMA2(acc[0][1], wA.x, hA.y); FMA2(acc[1][1], wA.y, hA.y);
        FMA2(acc[2][1], wB.x, hA.y); FMA2(acc[3][1], wB.y, hA.y);
        FMA2(acc[0][2], wA.x, hB.x); FMA2(acc[1][2], wA.y, hB.x);
        FMA2(acc[2][2], wB.x, hB.x); FMA2(acc[3][2], wB.y, hB.x);
        FMA2(acc[0][3], wA.x, hB.y); FMA2(acc[1][3], wA.y, hB.y);
        FMA2(acc[2][3], wB.x, hB.y); FMA2(acc[3][3], wB.y, hB.y);
    }
}

// ---- one GEMM segment (nch chunks), 4-deep bulk-copy pipeline ----
__device__ __forceinline__ void run_seg(ull acc[4][4], char* sm, unsigned mbar, int& ic,
                                        const float* wb, const float* hb0, const float* hb1,
                                        int nch, int hsw, int co, int bo, int kh) {
    #pragma unroll
    for (int j = 0; j < NS; j++) {
        const float* hs = (j < hsw) ? hb0 + j * 2048 : hb1 + (j - hsw) * 2048;
        issue_chunk(sm, mbar, ic + j, wb + j * 4096, hs);
    }
    for (int ch = 0; ch < nch; ch++) {
        int i = ic + ch;
        wait_chunk(mbar, i);
        compute_chunk(acc, sm, i & (NS - 1), co, bo, kh);
        __syncthreads();
        int nx = ch + NS;
        if (nx < nch) {
            const float* hs = (nx < hsw) ? hb0 + nx * 2048 : hb1 + (nx - hsw) * 2048;
            issue_chunk(sm, mbar, ic + nx, wb + nx * 4096, hs);
        }
    }
    ic += nch;
}

// ---- epilogue: accs -> gbuf[kh][col][b] (pitch 33) ----
__device__ __forceinline__ void store_gbuf(float* gbuf, ull acc[4][4],
                                           int co, int bo, int kh) {
    #pragma unroll
    for (int p = 0; p < 4; p++) {
        #pragma unroll
        for (int b = 0; b < 4; b++) {
            float2 v = *(float2*)&acc[p][b];
            gbuf[(kh * 128 + co + 2 * p) * 33 + bo + b]     = v.x;
            gbuf[(kh * 128 + co + 2 * p + 1) * 33 + bo + b] = v.y;
        }
    }
}

__global__ void __launch_bounds__(256, 1) lstm_persistent(
    const float* __restrict__ Wih0,     // [2048][128] = input LUT, natural layout
    const float* __restrict__ blin,
    const int* __restrict__ z, const int* __restrict__ nframes,
    float* __restrict__ out)
{
    extern __shared__ __align__(16) char sm[];
    float* gbuf = (float*)sm;   // 2*128*33 floats, aliased onto stage mem
    unsigned mbar = (unsigned)__cvta_generic_to_shared(sm + NS * STAGE);

    const int tid  = threadIdx.x;
    const int lane = tid & 31, wid = tid >> 5;
    const int kh = wid >> 2, wq = wid & 3;
    const int co = wq * 32 + (lane & 3) * 8;
    const int bo = (lane >> 2) * 4;
    const int blk = blockIdx.x;

    if (tid == 0) {
        #pragma unroll
        for (int s = 0; s < NS; s++)
            asm volatile("mbarrier.init.shared.b64 [%0], 1;" :: "r"(mbar + s * 8) : "memory");
    }
    __syncthreads();

    unsigned bar_t = 0;
    int ic = 0;

    if (blk < 128) {
        const int st = blk >> 3, bt = blk & 7, b0 = bt * 32;
        const int bl = tid & 31, uu4 = (tid >> 5) * 4;
        const int gb_ = b0 + bl;
        const float* w0 = g_w0p + st * 65536;
        const float* w1 = g_w1p + st * 131072;

        for (int t = 0; t <= NT; t++) {
            const int rd = t & 1, wr = rd ^ 1;

            // ===== phase A: layer 0 =====
            if (t < NT) {
                ull acc[4][4] = {};
                run_seg(acc, sm, mbar, ic, w0, g_h0d[rd] + bt * 32768, nullptr,
                        16, 16, co, bo, kh);
                store_gbuf(gbuf, acc, co, bo, kh);
                __syncthreads();

                int zp = (t > 0) ? z[gb_ * NT + t - 1] : 0;
                #pragma unroll
                for (int q = 0; q < 4; q++) {
                    int uu = uu4 + q, urow = st * 32 + uu, col = uu * 4;
                    float gi = gbuf[(col + 0) * 33 + bl] + gbuf[(128 + col + 0) * 33 + bl] + g_bs0[urow];
                    float gf = gbuf[(col + 1) * 33 + bl] + gbuf[(128 + col + 1) * 33 + bl] + g_bs0[512 + urow];
                    float gg = gbuf[(col + 2) * 33 + bl] + gbuf[(128 + col + 2) * 33 + bl] + g_bs0[1024 + urow];
                    float go = gbuf[(col + 3) * 33 + bl] + gbuf[(128 + col + 3) * 33 + bl] + g_bs0[1536 + urow];
                    if (t > 0) {
                        gi += Wih0[urow * 128 + zp];
                        gf += Wih0[(512 + urow) * 128 + zp];
                        gg += Wih0[(1024 + urow) * 128 + zp];
                        go += Wih0[(1536 + urow) * 128 + zp];
                    }
                    int cidx = urow * NB + gb_;
                    float c  = g_c0[cidx];
                    float cn = sigf(gf) * c + sigf(gi) * tanhf_fast(gg);
                    g_c0[cidx] = cn;
                    float hn = sigf(go) * tanhf_fast(cn);
                    int hoff = ((bt * 16 + (urow >> 5)) * 32 + (urow & 31)) * 64 + bl * 2;
                    *(float2*)&g_h0d[wr][hoff] = make_float2(hn, hn);
                }
            }
            bar_t += NBLK; grid_barrier(bar_t);

            // ===== phase B: layer 1 (32 chunks: h0 then h1) =====
            if (t < NT) {
                ull acc[4][4] = {};
                run_seg(acc, sm, mbar, ic, w1,
                        g_h0d[wr] + bt * 32768, g_h1d[rd] + bt * 32768,
                        32, 16, co, bo, kh);
                store_gbuf(gbuf, acc, co, bo, kh);
                __syncthreads();

                #pragma unroll
                for (int q = 0; q < 4; q++) {
                    int uu = uu4 + q, urow = st * 32 + uu, col = uu * 4;
                    float gi = gbuf[(col + 0) * 33 + bl] + gbuf[(128 + col + 0) * 33 + bl] + g_bs1[urow];
                    float gf = gbuf[(col + 1) * 33 + bl] + gbuf[(128 + col + 1) * 33 + bl] + g_bs1[512 + urow];
                    float gg = gbuf[(col + 2) * 33 + bl] + gbuf[(128 + col + 2) * 33 + bl] + g_bs1[1024 + urow];
                    float go = gbuf[(col + 3) * 33 + bl] + gbuf[(128 + col + 3) * 33 + bl] + g_bs1[1536 + urow];
                    int cidx = urow * NB + gb_;
                    float c  = g_c1[cidx];
                    float cn = sigf(gf) * c + sigf(gi) * tanhf_fast(gg);
                    g_c1[cidx] = cn;
                    float hn = sigf(go) * tanhf_fast(cn);
                    int hoff = ((bt * 16 + (urow >> 5)) * 32 + (urow & 31)) * 64 + bl * 2;
                    *(float2*)&g_h1d[wr][hoff] = make_float2(hn, hn);
                }
            }
            bar_t += NBLK; grid_barrier(bar_t);
        }
    } else {
        // ---------------- logits blocks: NLL for step t-1 in phase A ----------------
        const int bt = blk - 128, b0 = bt * 32;
        float nll[4];
        int nf4[4];
        #pragma unroll
        for (int bb = 0; bb < 4; bb++) {
            nll[bb] = 0.f;
            nf4[bb] = nframes[b0 + wid * 4 + bb];
        }

        for (int t = 0; t <= NT; t++) {
            const int rd = t & 1;
            if (t >= 1) {
                const int s_ = t - 1;
                ull acc[4][4] = {};
                run_seg(acc, sm, mbar, ic, g_wlt, g_h1d[rd] + bt * 32768, nullptr,
                        16, 16, co, bo, kh);
                store_gbuf(gbuf, acc, co, bo, kh);
                __syncthreads();

                #pragma unroll
                for (int bb = 0; bb < 4; bb++) {
                    int blr = wid * 4 + bb;
                    float lg[4];
                    #pragma unroll
                    for (int j = 0; j < 4; j++)
                        lg[j] = gbuf[(lane + 32 * j) * 33 + blr]
                              + gbuf[(128 + lane + 32 * j) * 33 + blr]
                              + blin[lane + 32 * j];
                    float m = fmaxf(fmaxf(lg[0], lg[1]), fmaxf(lg[2], lg[3]));
                    m = warp_max(m);
                    float se = 0.f;
                    #pragma unroll
                    for (int j = 0; j < 4; j++) se += __expf(lg[j] - m);
                    se = warp_sum(se);
                    float lse = m + logf(se);
                    int tgt = z[(b0 + blr) * NT + s_];
                    float tl = 0.f;
                    #pragma unroll
                    for (int j = 0; j < 4; j++)
                        if (lane + 32 * j == tgt) tl = lg[j];
                    tl = warp_sum(tl);
                    if (s_ < nf4[bb]) nll[bb] += (lse - tl);
                }
            }
            bar_t += NBLK; grid_barrier(bar_t);
            bar_t += NBLK; grid_barrier(bar_t);
        }

        if (lane == 0) {
            #pragma unroll
            for (int bb = 0; bb < 4; bb++)
                out[b0 + wid * 4 + bb] = nll[bb] * (1.0f / (float)NT);
        }
    }
}

extern "C" void kernel_launch(void* const* d_in, const int* in_sizes, int n_in,
                              void* d_out, int out_size) {
    const float* Wih0 = (const float*)d_in[0];
    const float* Whh0 = (const float*)d_in[1];
    const float* bih0 = (const float*)d_in[2];
    const float* bhh0 = (const float*)d_in[3];
    const float* Wih1 = (const float*)d_in[4];
    const float* Whh1 = (const float*)d_in[5];
    const float* bih1 = (const float*)d_in[6];
    const float* bhh1 = (const float*)d_in[7];
    const float* Wlin = (const float*)d_in[8];
    const float* blin = (const float*)d_in[9];
    const int*   z    = (const int*)d_in[10];
    const int*   nf   = (const int*)d_in[11];
    float* out = (float*)d_out;

    cudaFuncSetAttribute(lstm_persistent,
                         cudaFuncAttributeMaxDynamicSharedMemorySize, SMEM_DYN);
    kinit<<<256, 256>>>(Whh0, bih0, bhh0, Wih1, Whh1, bih1, bhh1, Wlin);
    lstm_persistent<<<NBLK, 256, SMEM_DYN>>>(Wih0, blin, z, nf, out);
}